// round 1
// baseline (speedup 1.0000x reference)
#include <cuda_runtime.h>
#include <cuda_bf16.h>
#include <cstdint>

#define GN 100000
#define GE 1600000
#define HEADS 4
#define ODIM 32
#define HO 128   /* HEADS*ODIM */
#define IND 128

// ---------------- scratch (device globals; no allocation allowed) ----------
__device__ float  g_h[(size_t)GN * HO];          // projected features, 51.2 MB
__device__ float4 g_ssrc[GN];                    // per-node src scores (4 heads)
__device__ float4 g_sdst[GN];                    // per-node dst scores
__device__ float4 g_denom[GN];                   // softmax denominators
__device__ float4 g_exps[GE];                    // per-edge exp(score), 25.6 MB

// ---------------- helpers ----------------
__device__ __forceinline__ void red4(float4* p, float4 v) {
    asm volatile("red.global.add.v4.f32 [%0], {%1,%2,%3,%4};"
                 :: "l"(p), "f"(v.x), "f"(v.y), "f"(v.z), "f"(v.w) : "memory");
}

__device__ __forceinline__ float lexp(float v) {
    v = (v >= 0.f) ? v : 0.2f * v;   // leaky_relu(0.2)
    return __expf(v);                // scores bounded ~[-4,3]; no max-shift needed
}

// ---------------- 0: zero denom + out aggregation region ----------------
__global__ void zero_kernel(float4* out4) {
    const int total = GN + GN * (HO / 4);   // denom + out region, in float4s
    for (int i = blockIdx.x * blockDim.x + threadIdx.x; i < total;
         i += gridDim.x * blockDim.x) {
        if (i < GN) g_denom[i] = make_float4(0.f, 0.f, 0.f, 0.f);
        else        out4[i - GN] = make_float4(0.f, 0.f, 0.f, 0.f);
    }
}

// ---------------- 1: h = x @ W^T  (fp32 tiled GEMM, 128x128 tile) ----------
__global__ void __launch_bounds__(256) gemm_kernel(const float* __restrict__ x,
                                                   const float* __restrict__ W) {
    __shared__ alignas(16) float sA[16 * 132];  // [k][row], padded
    __shared__ alignas(16) float sB[16 * 132];  // [k][col], padded
    const int tid = threadIdx.x;
    const int tx = tid & 15;        // col group: cols tx*8 .. tx*8+7
    const int ty = tid >> 4;        // row group: rows ty*8 .. ty*8+7
    const int rowBase = blockIdx.x * 128;

    float acc[8][8];
#pragma unroll
    for (int i = 0; i < 8; i++)
#pragma unroll
        for (int j = 0; j < 8; j++) acc[i][j] = 0.f;

    for (int kt = 0; kt < IND; kt += 16) {
#pragma unroll
        for (int half = 0; half < 2; half++) {
            int f = tid + half * 256;       // 0..511 float4 slots
            int r = f >> 2;                 // row (x) / col (W): 0..127
            int kq = f & 3;                 // which float4 in the 16-wide k tile
            int grow = rowBase + r;
            float4 v = (grow < GN)
                ? *(const float4*)(x + (size_t)grow * IND + kt + kq * 4)
                : make_float4(0.f, 0.f, 0.f, 0.f);
            sA[(kq * 4 + 0) * 132 + r] = v.x;
            sA[(kq * 4 + 1) * 132 + r] = v.y;
            sA[(kq * 4 + 2) * 132 + r] = v.z;
            sA[(kq * 4 + 3) * 132 + r] = v.w;
            float4 w = *(const float4*)(W + (size_t)r * IND + kt + kq * 4);
            sB[(kq * 4 + 0) * 132 + r] = w.x;
            sB[(kq * 4 + 1) * 132 + r] = w.y;
            sB[(kq * 4 + 2) * 132 + r] = w.z;
            sB[(kq * 4 + 3) * 132 + r] = w.w;
        }
        __syncthreads();
#pragma unroll
        for (int kk = 0; kk < 16; kk++) {
            float a[8], b[8];
            *(float4*)(a)     = *(const float4*)(sA + kk * 132 + ty * 8);
            *(float4*)(a + 4) = *(const float4*)(sA + kk * 132 + ty * 8 + 4);
            *(float4*)(b)     = *(const float4*)(sB + kk * 132 + tx * 8);
            *(float4*)(b + 4) = *(const float4*)(sB + kk * 132 + tx * 8 + 4);
#pragma unroll
            for (int i = 0; i < 8; i++)
#pragma unroll
                for (int j = 0; j < 8; j++) acc[i][j] += a[i] * b[j];
        }
        __syncthreads();
    }

#pragma unroll
    for (int i = 0; i < 8; i++) {
        int grow = rowBase + ty * 8 + i;
        if (grow < GN) {
            float* hp = g_h + (size_t)grow * HO + tx * 8;
            *(float4*)(hp)     = make_float4(acc[i][0], acc[i][1], acc[i][2], acc[i][3]);
            *(float4*)(hp + 4) = make_float4(acc[i][4], acc[i][5], acc[i][6], acc[i][7]);
        }
    }
}

// ---------------- 2: per-node attention scores ----------------
__global__ void scores_kernel(const float* __restrict__ a_src,
                              const float* __restrict__ a_dst) {
    int warp = (blockIdx.x * blockDim.x + threadIdx.x) >> 5;
    int lane = threadIdx.x & 31;
    if (warp >= GN) return;
    const float* hr = g_h + (size_t)warp * HO;
    float ss[HEADS], sd[HEADS];
#pragma unroll
    for (int hd = 0; hd < HEADS; hd++) {
        float v = hr[hd * ODIM + lane];
        float ps = v * a_src[hd * ODIM + lane];
        float pd = v * a_dst[hd * ODIM + lane];
#pragma unroll
        for (int o = 16; o; o >>= 1) {
            ps += __shfl_xor_sync(0xFFFFFFFFu, ps, o);
            pd += __shfl_xor_sync(0xFFFFFFFFu, pd, o);
        }
        ss[hd] = ps; sd[hd] = pd;
    }
    if (lane == 0) {
        g_ssrc[warp] = make_float4(ss[0], ss[1], ss[2], ss[3]);
        g_sdst[warp] = make_float4(sd[0], sd[1], sd[2], sd[3]);
    }
}

// ---------------- 3: edge scores -> exp, accumulate denominators ----------
__global__ void edge1_kernel(const int* __restrict__ ei,
                             const float* __restrict__ rw) {
    int e = blockIdx.x * blockDim.x + threadIdx.x;
    if (e >= GE) return;
    int s = ei[e];
    int d = ei[GE + e];
    float lw = __logf(rw[e] + 1e-8f);
    float4 a = g_ssrc[s];
    float4 b = g_sdst[d];
    float4 es;
    es.x = lexp(a.x + b.x + lw);
    es.y = lexp(a.y + b.y + lw);
    es.z = lexp(a.z + b.z + lw);
    es.w = lexp(a.w + b.w + lw);
    g_exps[e] = es;
    red4(&g_denom[d], es);
}

// ---------------- 4: normalize + scatter aggregation (warp per edge) ------
__global__ void edge2_kernel(const int* __restrict__ ei,
                             float* __restrict__ out,
                             float4* __restrict__ alpha_out,
                             int writeAlpha) {
    int gw = (blockIdx.x * blockDim.x + threadIdx.x) >> 5;
    int lane = threadIdx.x & 31;
    if (gw >= GE) return;
    int e = gw;
    int s = ei[e];
    int d = ei[GE + e];
    float4 es = g_exps[e];
    float4 dn = g_denom[d];
    float4 al;
    al.x = es.x / (dn.x + 1e-8f);
    al.y = es.y / (dn.y + 1e-8f);
    al.z = es.z / (dn.z + 1e-8f);
    al.w = es.w / (dn.w + 1e-8f);
    if (writeAlpha && lane == 0) alpha_out[e] = al;

    const float4* h4 = (const float4*)g_h;
    float4 hv = h4[(size_t)s * (HO / 4) + lane];
    // head = lane>>3 ; pick alpha component without a local-memory array
    float a = (lane & 16) ? ((lane & 8) ? al.w : al.z)
                          : ((lane & 8) ? al.y : al.x);
    float4 v = make_float4(hv.x * a, hv.y * a, hv.z * a, hv.w * a);
    red4((float4*)(out + (size_t)d * HO) + lane, v);
}

// ---------------- launch ----------------
extern "C" void kernel_launch(void* const* d_in, const int* in_sizes, int n_in,
                              void* d_out, int out_size) {
    const float* x     = (const float*)d_in[0];
    const float* W     = (const float*)d_in[1];
    const float* a_src = (const float*)d_in[2];
    const float* a_dst = (const float*)d_in[3];
    const int*   ei    = (const int*)d_in[4];
    const float* rw    = (const float*)d_in[5];
    float* out = (float*)d_out;

    int writeAlpha = (out_size >= GN * HO + GE * HEADS) ? 1 : 0;
    float4* alpha_out = (float4*)(out + (size_t)GN * HO);

    {   // zero denom + out aggregation region
        int total = GN + GN * (HO / 4);
        int blocks = (total + 255) / 256;
        zero_kernel<<<blocks, 256>>>((float4*)out);
    }
    {   // GEMM
        int blocks = (GN + 127) / 128;
        gemm_kernel<<<blocks, 256>>>(x, W);
    }
    {   // per-node scores: one warp per node
        int threads = 256;
        int blocks = (GN * 32 + threads - 1) / threads;
        scores_kernel<<<blocks, threads>>>(a_src, a_dst);
    }
    {   // edge pass 1
        int blocks = (GE + 255) / 256;
        edge1_kernel<<<blocks, 256>>>(ei, rw);
    }
    {   // edge pass 2: one warp per edge
        long long threads = (long long)GE * 32;
        int blocks = (int)((threads + 255) / 256);
        edge2_kernel<<<blocks, 256>>>(ei, out, alpha_out, writeAlpha);
    }
}

// round 2
// speedup vs baseline: 1.4435x; 1.4435x over previous
#include <cuda_runtime.h>
#include <cuda_bf16.h>
#include <cstdint>

#define GN 100000
#define GE 1600000
#define HEADS 4
#define ODIM 32
#define HO 128   /* HEADS*ODIM */
#define IND 128
#define NB 98    /* ceil(GN/1024) scan blocks */

// ---------------- scratch (device globals; no allocation allowed) ----------
__device__ float  g_h[(size_t)GN * HO];          // projected features, 51.2 MB
__device__ float4 g_ssrc[GN];                    // per-node src scores (4 heads)
__device__ float4 g_sdst[GN];                    // per-node dst scores
__device__ float4 g_denom[GN];                   // softmax denominators
__device__ int    g_deg[GN];                     // in-degree histogram
__device__ int    g_incl[GN];                    // per-block inclusive scan
__device__ int    g_bsum[NB];                    // block sums
__device__ int    g_bpref[NB];                   // inclusive scan of block sums
__device__ int    g_rowoff[GN + 1];              // CSR row offsets (by dst)
__device__ int    g_cursor[GN];                  // scatter cursors
__device__ int    g_csr_src[GE];                 // CSR: src node per slot
__device__ float  g_csr_lw[GE];                  // CSR: log(rw+eps) per slot

// ---------------- helpers ----------------
__device__ __forceinline__ float lexp(float v) {
    v = (v >= 0.f) ? v : 0.2f * v;   // leaky_relu(0.2)
    return __expf(v);                // scores bounded; no max-shift needed
}

// ---------------- 0: zero degree counters ----------------
__global__ void zero_deg_kernel() {
    int i = blockIdx.x * blockDim.x + threadIdx.x;
    if (i < GN) g_deg[i] = 0;
}

// ---------------- 1: h = x @ W^T  (fp32 tiled GEMM, 128x128 tile) ----------
__global__ void __launch_bounds__(256) gemm_kernel(const float* __restrict__ x,
                                                   const float* __restrict__ W) {
    __shared__ alignas(16) float sA[16 * 132];  // [k][row], padded
    __shared__ alignas(16) float sB[16 * 132];  // [k][col], padded
    const int tid = threadIdx.x;
    const int tx = tid & 15;
    const int ty = tid >> 4;
    const int rowBase = blockIdx.x * 128;

    float acc[8][8];
#pragma unroll
    for (int i = 0; i < 8; i++)
#pragma unroll
        for (int j = 0; j < 8; j++) acc[i][j] = 0.f;

    for (int kt = 0; kt < IND; kt += 16) {
#pragma unroll
        for (int half = 0; half < 2; half++) {
            int f = tid + half * 256;
            int r = f >> 2;
            int kq = f & 3;
            int grow = rowBase + r;
            float4 v = (grow < GN)
                ? *(const float4*)(x + (size_t)grow * IND + kt + kq * 4)
                : make_float4(0.f, 0.f, 0.f, 0.f);
            sA[(kq * 4 + 0) * 132 + r] = v.x;
            sA[(kq * 4 + 1) * 132 + r] = v.y;
            sA[(kq * 4 + 2) * 132 + r] = v.z;
            sA[(kq * 4 + 3) * 132 + r] = v.w;
            float4 w = *(const float4*)(W + (size_t)r * IND + kt + kq * 4);
            sB[(kq * 4 + 0) * 132 + r] = w.x;
            sB[(kq * 4 + 1) * 132 + r] = w.y;
            sB[(kq * 4 + 2) * 132 + r] = w.z;
            sB[(kq * 4 + 3) * 132 + r] = w.w;
        }
        __syncthreads();
#pragma unroll
        for (int kk = 0; kk < 16; kk++) {
            float a[8], b[8];
            *(float4*)(a)     = *(const float4*)(sA + kk * 132 + ty * 8);
            *(float4*)(a + 4) = *(const float4*)(sA + kk * 132 + ty * 8 + 4);
            *(float4*)(b)     = *(const float4*)(sB + kk * 132 + tx * 8);
            *(float4*)(b + 4) = *(const float4*)(sB + kk * 132 + tx * 8 + 4);
#pragma unroll
            for (int i = 0; i < 8; i++)
#pragma unroll
                for (int j = 0; j < 8; j++) acc[i][j] += a[i] * b[j];
        }
        __syncthreads();
    }

#pragma unroll
    for (int i = 0; i < 8; i++) {
        int grow = rowBase + ty * 8 + i;
        if (grow < GN) {
            float* hp = g_h + (size_t)grow * HO + tx * 8;
            *(float4*)(hp)     = make_float4(acc[i][0], acc[i][1], acc[i][2], acc[i][3]);
            *(float4*)(hp + 4) = make_float4(acc[i][4], acc[i][5], acc[i][6], acc[i][7]);
        }
    }
}

// ---------------- 2: per-node attention scores ----------------
__global__ void scores_kernel(const float* __restrict__ a_src,
                              const float* __restrict__ a_dst) {
    int warp = (blockIdx.x * blockDim.x + threadIdx.x) >> 5;
    int lane = threadIdx.x & 31;
    if (warp >= GN) return;
    const float* hr = g_h + (size_t)warp * HO;
    float ss[HEADS], sd[HEADS];
#pragma unroll
    for (int hd = 0; hd < HEADS; hd++) {
        float v = hr[hd * ODIM + lane];
        float ps = v * a_src[hd * ODIM + lane];
        float pd = v * a_dst[hd * ODIM + lane];
#pragma unroll
        for (int o = 16; o; o >>= 1) {
            ps += __shfl_xor_sync(0xFFFFFFFFu, ps, o);
            pd += __shfl_xor_sync(0xFFFFFFFFu, pd, o);
        }
        ss[hd] = ps; sd[hd] = pd;
    }
    if (lane == 0) {
        g_ssrc[warp] = make_float4(ss[0], ss[1], ss[2], ss[3]);
        g_sdst[warp] = make_float4(sd[0], sd[1], sd[2], sd[3]);
    }
}

// ---------------- 3: degree histogram over dst ----------------
__global__ void hist_kernel(const int* __restrict__ ei) {
    int e = blockIdx.x * blockDim.x + threadIdx.x;
    if (e >= GE) return;
    atomicAdd(&g_deg[ei[GE + e]], 1);
}

// ---------------- 4a: per-block inclusive scan ----------------
__global__ void __launch_bounds__(1024) scan1_kernel() {
    int i = blockIdx.x * 1024 + threadIdx.x;
    int v = (i < GN) ? g_deg[i] : 0;
    int lane = threadIdx.x & 31, w = threadIdx.x >> 5;
    int s = v;
#pragma unroll
    for (int o = 1; o < 32; o <<= 1) {
        int t = __shfl_up_sync(0xFFFFFFFFu, s, o);
        if (lane >= o) s += t;
    }
    __shared__ int ws[32];
    if (lane == 31) ws[w] = s;
    __syncthreads();
    if (w == 0) {
        int t = ws[lane];
#pragma unroll
        for (int o = 1; o < 32; o <<= 1) {
            int u = __shfl_up_sync(0xFFFFFFFFu, t, o);
            if (lane >= o) t += u;
        }
        ws[lane] = t;
    }
    __syncthreads();
    if (w > 0) s += ws[w - 1];
    if (i < GN) g_incl[i] = s;
    if (threadIdx.x == 1023) g_bsum[blockIdx.x] = s;
}

// ---------------- 4b: scan block sums (tiny, serial) ----------------
__global__ void scan2_kernel() {
    if (threadIdx.x == 0 && blockIdx.x == 0) {
        int run = 0;
        for (int b = 0; b < NB; b++) { run += g_bsum[b]; g_bpref[b] = run; }
    }
}

// ---------------- 4c: finalize exclusive row offsets + cursors ------------
__global__ void scan3_kernel() {
    int i = blockIdx.x * blockDim.x + threadIdx.x;
    if (i >= GN) return;
    int b = i >> 10;
    int excl = g_incl[i] - g_deg[i] + (b > 0 ? g_bpref[b - 1] : 0);
    g_rowoff[i] = excl;
    g_cursor[i] = excl;
    if (i == 0) g_rowoff[GN] = GE;
}

// ---------------- 5: scatter edges into CSR (by dst) ----------------
__global__ void scatter_kernel(const int* __restrict__ ei,
                               const float* __restrict__ rw) {
    int e = blockIdx.x * blockDim.x + threadIdx.x;
    if (e >= GE) return;
    int s = ei[e];
    int d = ei[GE + e];
    int pos = atomicAdd(&g_cursor[d], 1);
    g_csr_src[pos] = s;
    g_csr_lw[pos] = __logf(rw[e] + 1e-8f);
}

// ---------------- 6: atomic-free aggregation, one warp per dst node -------
__global__ void __launch_bounds__(256) agg_kernel(float* __restrict__ out) {
    int node = (blockIdx.x * blockDim.x + threadIdx.x) >> 5;
    int lane = threadIdx.x & 31;
    if (node >= GN) return;
    int head = lane >> 3;

    int beg = g_rowoff[node];
    int end = g_rowoff[node + 1];
    float sd = ((const float*)&g_sdst[node])[head];

    const float4* h4 = (const float4*)g_h;
    const float* ssrc_f = (const float*)g_ssrc;

    float denom = 0.f;
    float4 acc = make_float4(0.f, 0.f, 0.f, 0.f);

    // software-pipelined edge loop (loads for e+1 issued before body of e)
    int s_cur = 0; float lw_cur = 0.f;
    if (beg < end) { s_cur = g_csr_src[beg]; lw_cur = g_csr_lw[beg]; }
    for (int e = beg; e < end; e++) {
        int s_nxt = 0; float lw_nxt = 0.f;
        if (e + 1 < end) { s_nxt = g_csr_src[e + 1]; lw_nxt = g_csr_lw[e + 1]; }
        float a_s = ssrc_f[(size_t)s_cur * 4 + head];
        float4 hv = h4[(size_t)s_cur * (HO / 4) + lane];
        float p = a_s + sd + lw_cur;
        float ex = lexp(p);
        denom += ex;
        acc.x = fmaf(ex, hv.x, acc.x);
        acc.y = fmaf(ex, hv.y, acc.y);
        acc.z = fmaf(ex, hv.z, acc.z);
        acc.w = fmaf(ex, hv.w, acc.w);
        s_cur = s_nxt; lw_cur = lw_nxt;
    }

    float inv = 1.f / (denom + 1e-8f);
    float4 o = make_float4(acc.x * inv, acc.y * inv, acc.z * inv, acc.w * inv);
    ((float4*)out)[(size_t)node * (HO / 4) + lane] = o;
    if ((lane & 7) == 0) ((float*)&g_denom[node])[head] = denom;
}

// ---------------- 7: alpha output (original edge order) ----------------
__global__ void alpha_kernel(const int* __restrict__ ei,
                             const float* __restrict__ rw,
                             float4* __restrict__ alpha_out) {
    int e = blockIdx.x * blockDim.x + threadIdx.x;
    if (e >= GE) return;
    int s = ei[e];
    int d = ei[GE + e];
    float lw = __logf(rw[e] + 1e-8f);
    float4 a = g_ssrc[s];
    float4 b = g_sdst[d];
    float4 dn = g_denom[d];
    float4 al;
    al.x = lexp(a.x + b.x + lw) / (dn.x + 1e-8f);
    al.y = lexp(a.y + b.y + lw) / (dn.y + 1e-8f);
    al.z = lexp(a.z + b.z + lw) / (dn.z + 1e-8f);
    al.w = lexp(a.w + b.w + lw) / (dn.w + 1e-8f);
    alpha_out[e] = al;
}

// ---------------- launch ----------------
extern "C" void kernel_launch(void* const* d_in, const int* in_sizes, int n_in,
                              void* d_out, int out_size) {
    const float* x     = (const float*)d_in[0];
    const float* W     = (const float*)d_in[1];
    const float* a_src = (const float*)d_in[2];
    const float* a_dst = (const float*)d_in[3];
    const int*   ei    = (const int*)d_in[4];
    const float* rw    = (const float*)d_in[5];
    float* out = (float*)d_out;

    int writeAlpha = (out_size >= GN * HO + GE * HEADS) ? 1 : 0;
    float4* alpha_out = (float4*)(out + (size_t)GN * HO);

    zero_deg_kernel<<<(GN + 255) / 256, 256>>>();
    gemm_kernel<<<(GN + 127) / 128, 256>>>(x, W);
    scores_kernel<<<(GN * 32 + 255) / 256, 256>>>(a_src, a_dst);
    hist_kernel<<<(GE + 255) / 256, 256>>>(ei);
    scan1_kernel<<<NB, 1024>>>();
    scan2_kernel<<<1, 32>>>();
    scan3_kernel<<<(GN + 255) / 256, 256>>>();
    scatter_kernel<<<(GE + 255) / 256, 256>>>(ei, rw);
    agg_kernel<<<(int)(((long long)GN * 32 + 255) / 256), 256>>>(out);
    if (writeAlpha)
        alpha_kernel<<<(GE + 255) / 256, 256>>>(ei, rw, alpha_out);
}

// round 5
// speedup vs baseline: 1.4738x; 1.0209x over previous
#include <cuda_runtime.h>
#include <cuda_bf16.h>
#include <cstdint>

#define GN 100000
#define GE 1600000
#define HEADS 4
#define ODIM 32
#define HO 128   /* HEADS*ODIM */
#define IND 128
#define NB 98    /* ceil(GN/1024) scan blocks */
#define LDT 136  /* padded bf16 row stride for smem tiles */

// ---------------- scratch (device globals; no allocation allowed) ----------
__device__ float  g_h[(size_t)GN * HO];          // projected features, 51.2 MB
__device__ float4 g_ssrc[GN];                    // per-node src scores (4 heads)
__device__ float4 g_sdst[GN];                    // per-node dst scores
__device__ float4 g_denom[GN];                   // softmax denominators
__device__ int    g_deg[GN];                     // in-degree histogram
__device__ int    g_incl[GN];                    // per-block inclusive scan
__device__ int    g_bsum[NB];                    // block sums
__device__ int    g_bpref[NB];                   // inclusive scan of block sums
__device__ int    g_rowoff[GN + 1];              // CSR row offsets (by dst)
__device__ int    g_cursor[GN];                  // scatter cursors
__device__ int    g_csr_src[GE];                 // CSR: src node per slot
__device__ float  g_csr_lw[GE];                  // CSR: log(rw+eps) per slot

// ---------------- helpers ----------------
__device__ __forceinline__ uint32_t smem_u32(const void* p) {
    uint32_t a;
    asm("{ .reg .u64 t; cvta.to.shared.u64 t, %1; cvt.u32.u64 %0, t; }"
        : "=r"(a) : "l"(p));
    return a;
}
__device__ __forceinline__ void ldsm4(uint32_t& r0, uint32_t& r1,
                                      uint32_t& r2, uint32_t& r3, uint32_t addr) {
    asm volatile("ldmatrix.sync.aligned.m8n8.x4.shared.b16 {%0,%1,%2,%3}, [%4];"
                 : "=r"(r0), "=r"(r1), "=r"(r2), "=r"(r3) : "r"(addr));
}
__device__ __forceinline__ void mma16816(float* c, uint32_t a0, uint32_t a1,
                                         uint32_t a2, uint32_t a3,
                                         uint32_t b0, uint32_t b1) {
    asm volatile("mma.sync.aligned.m16n8k16.row.col.f32.bf16.bf16.f32 "
                 "{%0,%1,%2,%3}, {%4,%5,%6,%7}, {%8,%9}, {%0,%1,%2,%3};"
                 : "+f"(c[0]), "+f"(c[1]), "+f"(c[2]), "+f"(c[3])
                 : "r"(a0), "r"(a1), "r"(a2), "r"(a3), "r"(b0), "r"(b1));
}
__device__ __forceinline__ void split2(float v, __nv_bfloat16& h, __nv_bfloat16& l) {
    h = __float2bfloat16(v);
    l = __float2bfloat16(v - __bfloat162float(h));
}
__device__ __forceinline__ float lexp(float v) {
    v = (v >= 0.f) ? v : 0.2f * v;   // leaky_relu(0.2)
    return __expf(v);                // scores bounded; no max-shift needed
}

// ---------------- 0: zero degree counters ----------------
__global__ void zero_deg_kernel() {
    int i = blockIdx.x * blockDim.x + threadIdx.x;
    if (i < GN) g_deg[i] = 0;
}

// ---- 1: h = x @ W^T via mma.sync split-bf16 (hh + hl + lh), fused scores --
__global__ void __launch_bounds__(256) gemm_mma_kernel(const float* __restrict__ x,
                                                       const float* __restrict__ W,
                                                       const float* __restrict__ a_src,
                                                       const float* __restrict__ a_dst) {
    extern __shared__ char smem[];
    __nv_bfloat16* sAh = (__nv_bfloat16*)smem;
    __nv_bfloat16* sAl = sAh + 128 * LDT;
    __nv_bfloat16* sWh = sAl + 128 * LDT;
    __nv_bfloat16* sWl = sWh + 128 * LDT;

    const int tid = threadIdx.x;
    const int wid = tid >> 5;
    const int lane = tid & 31;
    const int rowBase = blockIdx.x * 128;

    // load + split-convert x tile and full W into padded smem
    for (int it = tid; it < 4096; it += 256) {
        int row = it >> 5;
        int col = (it & 31) * 4;
        int grow = rowBase + row;
        float4 v = (grow < GN) ? *(const float4*)(x + (size_t)grow * IND + col)
                               : make_float4(0.f, 0.f, 0.f, 0.f);
        __nv_bfloat16 h0, h1, h2, h3, l0, l1, l2, l3;
        split2(v.x, h0, l0); split2(v.y, h1, l1);
        split2(v.z, h2, l2); split2(v.w, h3, l3);
        int o = row * LDT + col;
        *(__nv_bfloat162*)(sAh + o)     = __nv_bfloat162(h0, h1);
        *(__nv_bfloat162*)(sAh + o + 2) = __nv_bfloat162(h2, h3);
        *(__nv_bfloat162*)(sAl + o)     = __nv_bfloat162(l0, l1);
        *(__nv_bfloat162*)(sAl + o + 2) = __nv_bfloat162(l2, l3);

        float4 w = *(const float4*)(W + (size_t)row * IND + col);
        split2(w.x, h0, l0); split2(w.y, h1, l1);
        split2(w.z, h2, l2); split2(w.w, h3, l3);
        *(__nv_bfloat162*)(sWh + o)     = __nv_bfloat162(h0, h1);
        *(__nv_bfloat162*)(sWh + o + 2) = __nv_bfloat162(h2, h3);
        *(__nv_bfloat162*)(sWl + o)     = __nv_bfloat162(l0, l1);
        *(__nv_bfloat162*)(sWl + o + 2) = __nv_bfloat162(l2, l3);
    }
    __syncthreads();

    float acc[64];
#pragma unroll
    for (int i = 0; i < 64; i++) acc[i] = 0.f;

    // per-lane ldmatrix address components
    const int aRow = wid * 16 + (lane & 15);            // A: rows of this warp's 16
    const int aKH  = (lane >> 4) * 8;                   // A: k half select
    const int bRow = (lane & 7) + ((lane >> 4) << 3);   // B: n row within 16-pair
    const int bKH  = ((lane >> 3) & 1) * 8;             // B: k half select

#pragma unroll
    for (int p = 0; p < 3; p++) {
        const __nv_bfloat16* At = (p == 2) ? sAl : sAh;
        const __nv_bfloat16* Bt = (p == 1) ? sWl : sWh;
        uint32_t aBase = smem_u32(At) + (uint32_t)(aRow * LDT + aKH) * 2u;
        uint32_t bBase = smem_u32(Bt) + (uint32_t)(bRow * LDT + bKH) * 2u;
#pragma unroll
        for (int ks = 0; ks < 8; ks++) {
            uint32_t a0, a1, a2, a3;
            ldsm4(a0, a1, a2, a3, aBase + ks * 32);
#pragma unroll
            for (int tp = 0; tp < 8; tp++) {
                uint32_t b0, b1, b2, b3;
                ldsm4(b0, b1, b2, b3, bBase + (uint32_t)(tp * 16 * LDT) * 2u + ks * 32);
                mma16816(acc + (2 * tp) * 4,     a0, a1, a2, a3, b0, b1);
                mma16816(acc + (2 * tp + 1) * 4, a0, a1, a2, a3, b2, b3);
            }
        }
    }

    // epilogue: write h rows + fused per-node scores
    const int g = lane >> 2, tg = lane & 3;
    const int rA = rowBase + wid * 16 + g;
    const int rB = rA + 8;
    const bool vA = rA < GN, vB = rB < GN;

    if (vA) {
        float* hp = g_h + (size_t)rA * HO;
#pragma unroll
        for (int t = 0; t < 16; t++)
            *(float2*)(hp + t * 8 + tg * 2) = make_float2(acc[t * 4], acc[t * 4 + 1]);
    }
    if (vB) {
        float* hp = g_h + (size_t)rB * HO;
#pragma unroll
        for (int t = 0; t < 16; t++)
            *(float2*)(hp + t * 8 + tg * 2) = make_float2(acc[t * 4 + 2], acc[t * 4 + 3]);
    }

    float kAs = 0.f, kAd = 0.f, kBs = 0.f, kBd = 0.f;
#pragma unroll
    for (int h = 0; h < 4; h++) {
        float pAs = 0.f, pAd = 0.f, pBs = 0.f, pBd = 0.f;
#pragma unroll
        for (int tt = 0; tt < 4; tt++) {
            int t = h * 4 + tt;
            int col = t * 8 + tg * 2;
            float as0 = a_src[col], as1 = a_src[col + 1];
            float ad0 = a_dst[col], ad1 = a_dst[col + 1];
            pAs += acc[t * 4] * as0 + acc[t * 4 + 1] * as1;
            pAd += acc[t * 4] * ad0 + acc[t * 4 + 1] * ad1;
            pBs += acc[t * 4 + 2] * as0 + acc[t * 4 + 3] * as1;
            pBd += acc[t * 4 + 2] * ad0 + acc[t * 4 + 3] * ad1;
        }
        pAs += __shfl_xor_sync(0xFFFFFFFFu, pAs, 1);
        pAs += __shfl_xor_sync(0xFFFFFFFFu, pAs, 2);
        pAd += __shfl_xor_sync(0xFFFFFFFFu, pAd, 1);
        pAd += __shfl_xor_sync(0xFFFFFFFFu, pAd, 2);
        pBs += __shfl_xor_sync(0xFFFFFFFFu, pBs, 1);
        pBs += __shfl_xor_sync(0xFFFFFFFFu, pBs, 2);
        pBd += __shfl_xor_sync(0xFFFFFFFFu, pBd, 1);
        pBd += __shfl_xor_sync(0xFFFFFFFFu, pBd, 2);
        if (tg == h) { kAs = pAs; kAd = pAd; kBs = pBs; kBd = pBd; }
    }
    if (vA) {
        ((float*)&g_ssrc[rA])[tg] = kAs;
        ((float*)&g_sdst[rA])[tg] = kAd;
    }
    if (vB) {
        ((float*)&g_ssrc[rB])[tg] = kBs;
        ((float*)&g_sdst[rB])[tg] = kBd;
    }
}

// ---------------- 3: degree histogram over dst ----------------
__global__ void hist_kernel(const int* __restrict__ ei) {
    int e = blockIdx.x * blockDim.x + threadIdx.x;
    if (e >= GE) return;
    atomicAdd(&g_deg[ei[GE + e]], 1);
}

// ---------------- 4a: per-block inclusive scan ----------------
__global__ void __launch_bounds__(1024) scan1_kernel() {
    int i = blockIdx.x * 1024 + threadIdx.x;
    int v = (i < GN) ? g_deg[i] : 0;
    int lane = threadIdx.x & 31, w = threadIdx.x >> 5;
    int s = v;
#pragma unroll
    for (int o = 1; o < 32; o <<= 1) {
        int t = __shfl_up_sync(0xFFFFFFFFu, s, o);
        if (lane >= o) s += t;
    }
    __shared__ int ws[32];
    if (lane == 31) ws[w] = s;
    __syncthreads();
    if (w == 0) {
        int t = ws[lane];
#pragma unroll
        for (int o = 1; o < 32; o <<= 1) {
            int u = __shfl_up_sync(0xFFFFFFFFu, t, o);
            if (lane >= o) t += u;
        }
        ws[lane] = t;
    }
    __syncthreads();
    if (w > 0) s += ws[w - 1];
    if (i < GN) g_incl[i] = s;
    if (threadIdx.x == 1023) g_bsum[blockIdx.x] = s;
}

// ---------------- 4b: scan block sums (tiny, serial) ----------------
__global__ void scan2_kernel() {
    if (threadIdx.x == 0 && blockIdx.x == 0) {
        int run = 0;
        for (int b = 0; b < NB; b++) { run += g_bsum[b]; g_bpref[b] = run; }
    }
}

// ---------------- 4c: finalize exclusive row offsets + cursors ------------
__global__ void scan3_kernel() {
    int i = blockIdx.x * blockDim.x + threadIdx.x;
    if (i >= GN) return;
    int b = i >> 10;
    int excl = g_incl[i] - g_deg[i] + (b > 0 ? g_bpref[b - 1] : 0);
    g_rowoff[i] = excl;
    g_cursor[i] = excl;
    if (i == 0) g_rowoff[GN] = GE;
}

// ---------------- 5: scatter edges into CSR (by dst) ----------------
__global__ void scatter_kernel(const int* __restrict__ ei,
                               const float* __restrict__ rw) {
    int e = blockIdx.x * blockDim.x + threadIdx.x;
    if (e >= GE) return;
    int s = ei[e];
    int d = ei[GE + e];
    int pos = atomicAdd(&g_cursor[d], 1);
    g_csr_src[pos] = s;
    g_csr_lw[pos] = __logf(rw[e] + 1e-8f);
}

// ---------------- 6: atomic-free aggregation, one warp per dst node -------
__global__ void __launch_bounds__(256) agg_kernel(float* __restrict__ out) {
    int node = (blockIdx.x * blockDim.x + threadIdx.x) >> 5;
    int lane = threadIdx.x & 31;
    if (node >= GN) return;
    int head = lane >> 3;

    int beg = g_rowoff[node];
    int end = g_rowoff[node + 1];
    float sd = ((const float*)&g_sdst[node])[head];

    const float4* h4 = (const float4*)g_h;
    const float* ssrc_f = (const float*)g_ssrc;

    float denom = 0.f;
    float4 acc = make_float4(0.f, 0.f, 0.f, 0.f);

    int s_cur = 0; float lw_cur = 0.f;
    if (beg < end) { s_cur = g_csr_src[beg]; lw_cur = g_csr_lw[beg]; }
    for (int e = beg; e < end; e++) {
        int s_nxt = 0; float lw_nxt = 0.f;
        if (e + 1 < end) { s_nxt = g_csr_src[e + 1]; lw_nxt = g_csr_lw[e + 1]; }
        float a_s = ssrc_f[(size_t)s_cur * 4 + head];
        float4 hv = h4[(size_t)s_cur * (HO / 4) + lane];
        float p = a_s + sd + lw_cur;
        float ex = lexp(p);
        denom += ex;
        acc.x = fmaf(ex, hv.x, acc.x);
        acc.y = fmaf(ex, hv.y, acc.y);
        acc.z = fmaf(ex, hv.z, acc.z);
        acc.w = fmaf(ex, hv.w, acc.w);
        s_cur = s_nxt; lw_cur = lw_nxt;
    }

    float inv = 1.f / (denom + 1e-8f);
    float4 o = make_float4(acc.x * inv, acc.y * inv, acc.z * inv, acc.w * inv);
    ((float4*)out)[(size_t)node * (HO / 4) + lane] = o;
    if ((lane & 7) == 0) ((float*)&g_denom[node])[head] = denom;
}

// ---------------- 7: alpha output (original edge order) ----------------
__global__ void alpha_kernel(const int* __restrict__ ei,
                             const float* __restrict__ rw,
                             float4* __restrict__ alpha_out) {
    int e = blockIdx.x * blockDim.x + threadIdx.x;
    if (e >= GE) return;
    int s = ei[e];
    int d = ei[GE + e];
    float lw = __logf(rw[e] + 1e-8f);
    float4 a = g_ssrc[s];
    float4 b = g_sdst[d];
    float4 dn = g_denom[d];
    float4 al;
    al.x = lexp(a.x + b.x + lw) / (dn.x + 1e-8f);
    al.y = lexp(a.y + b.y + lw) / (dn.y + 1e-8f);
    al.z = lexp(a.z + b.z + lw) / (dn.z + 1e-8f);
    al.w = lexp(a.w + b.w + lw) / (dn.w + 1e-8f);
    alpha_out[e] = al;
}

// ---------------- launch ----------------
#define GEMM_SMEM (4 * 128 * LDT * 2)

extern "C" void kernel_launch(void* const* d_in, const int* in_sizes, int n_in,
                              void* d_out, int out_size) {
    const float* x     = (const float*)d_in[0];
    const float* W     = (const float*)d_in[1];
    const float* a_src = (const float*)d_in[2];
    const float* a_dst = (const float*)d_in[3];
    const int*   ei    = (const int*)d_in[4];
    const float* rw    = (const float*)d_in[5];
    float* out = (float*)d_out;

    int writeAlpha = (out_size >= GN * HO + GE * HEADS) ? 1 : 0;
    float4* alpha_out = (float4*)(out + (size_t)GN * HO);

    cudaFuncSetAttribute(gemm_mma_kernel,
                         cudaFuncAttributeMaxDynamicSharedMemorySize, GEMM_SMEM);

    zero_deg_kernel<<<(GN + 255) / 256, 256>>>();
    gemm_mma_kernel<<<(GN + 127) / 128, 256, GEMM_SMEM>>>(x, W, a_src, a_dst);
    hist_kernel<<<(GE + 255) / 256, 256>>>(ei);
    scan1_kernel<<<NB, 1024>>>();
    scan2_kernel<<<1, 32>>>();
    scan3_kernel<<<(GN + 255) / 256, 256>>>();
    scatter_kernel<<<(GE + 255) / 256, 256>>>(ei, rw);
    agg_kernel<<<(int)(((long long)GN * 32 + 255) / 256), 256>>>(out);
    if (writeAlpha)
        alpha_kernel<<<(GE + 255) / 256, 256>>>(ei, rw, alpha_out);
}

// round 7
// speedup vs baseline: 1.6916x; 1.1478x over previous
#include <cuda_runtime.h>
#include <cuda_bf16.h>
#include <cstdint>

#define GN 100000
#define GE 1600000
#define HEADS 4
#define ODIM 32
#define HO 128   /* HEADS*ODIM */
#define IND 128
#define NB 98    /* ceil(GN/1024) scan blocks */
#define LDT 136  /* padded bf16 row stride for smem tiles */

// ---------------- scratch (device globals; no allocation allowed) ----------
__device__ float  g_h[(size_t)GN * HO];          // projected features, 51.2 MB
__device__ float4 g_ssrc[GN];                    // per-node src scores (4 heads)
__device__ float4 g_sddn[2 * GN];                // [2n]=sdst, [2n+1]=denom (32B pair)
__device__ int    g_deg[GN];                     // in-degree histogram
__device__ int    g_incl[GN];                    // per-block inclusive scan
__device__ int    g_bsum[NB];                    // block sums
__device__ int    g_bpref[NB];                   // inclusive scan of block sums
__device__ int    g_rowoff[GN + 1];              // CSR row offsets (by dst)
__device__ int    g_cursor[GN];                  // scatter cursors
__device__ int2   g_csr[GE];                     // CSR: (src, log-weight bits)

// ---------------- helpers ----------------
__device__ __forceinline__ uint32_t smem_u32(const void* p) {
    uint32_t a;
    asm("{ .reg .u64 t; cvta.to.shared.u64 t, %1; cvt.u32.u64 %0, t; }"
        : "=r"(a) : "l"(p));
    return a;
}
__device__ __forceinline__ void ldsm4(uint32_t& r0, uint32_t& r1,
                                      uint32_t& r2, uint32_t& r3, uint32_t addr) {
    asm volatile("ldmatrix.sync.aligned.m8n8.x4.shared.b16 {%0,%1,%2,%3}, [%4];"
                 : "=r"(r0), "=r"(r1), "=r"(r2), "=r"(r3) : "r"(addr));
}
__device__ __forceinline__ void mma16816(float* c, uint32_t a0, uint32_t a1,
                                         uint32_t a2, uint32_t a3,
                                         uint32_t b0, uint32_t b1) {
    asm volatile("mma.sync.aligned.m16n8k16.row.col.f32.bf16.bf16.f32 "
                 "{%0,%1,%2,%3}, {%4,%5,%6,%7}, {%8,%9}, {%0,%1,%2,%3};"
                 : "+f"(c[0]), "+f"(c[1]), "+f"(c[2]), "+f"(c[3])
                 : "r"(a0), "r"(a1), "r"(a2), "r"(a3), "r"(b0), "r"(b1));
}
__device__ __forceinline__ void split2(float v, __nv_bfloat16& h, __nv_bfloat16& l) {
    h = __float2bfloat16(v);
    l = __float2bfloat16(v - __bfloat162float(h));
}
__device__ __forceinline__ float lexp(float v) {
    v = (v >= 0.f) ? v : 0.2f * v;   // leaky_relu(0.2)
    return __expf(v);                // scores bounded; no max-shift needed
}

// ---------------- zero degree counters ----------------
__global__ void zero_deg_kernel() {
    int i = blockIdx.x * blockDim.x + threadIdx.x;
    if (i < GN) g_deg[i] = 0;
}

// ---------------- degree histogram over dst (2 edges/thread) --------------
__global__ void hist_kernel(const int* __restrict__ ei) {
    int i = blockIdx.x * blockDim.x + threadIdx.x;
    if (i >= GE / 2) return;
    int2 d2 = ((const int2*)(ei + GE))[i];
    atomicAdd(&g_deg[d2.x], 1);
    atomicAdd(&g_deg[d2.y], 1);
}

// ---------------- per-block inclusive scan ----------------
__global__ void __launch_bounds__(1024) scan1_kernel() {
    int i = blockIdx.x * 1024 + threadIdx.x;
    int v = (i < GN) ? g_deg[i] : 0;
    int lane = threadIdx.x & 31, w = threadIdx.x >> 5;
    int s = v;
#pragma unroll
    for (int o = 1; o < 32; o <<= 1) {
        int t = __shfl_up_sync(0xFFFFFFFFu, s, o);
        if (lane >= o) s += t;
    }
    __shared__ int ws[32];
    if (lane == 31) ws[w] = s;
    __syncthreads();
    if (w == 0) {
        int t = ws[lane];
#pragma unroll
        for (int o = 1; o < 32; o <<= 1) {
            int u = __shfl_up_sync(0xFFFFFFFFu, t, o);
            if (lane >= o) t += u;
        }
        ws[lane] = t;
    }
    __syncthreads();
    if (w > 0) s += ws[w - 1];
    if (i < GN) g_incl[i] = s;
    if (threadIdx.x == 1023) g_bsum[blockIdx.x] = s;
}

// ---- h = x @ W^T via mma.sync split-bf16 (hh + hl + lh), fused scores ----
// (slot 4 in launch order so ncu's fixed profiling slot captures it)
__global__ void __launch_bounds__(256) gemm_mma_kernel(const float* __restrict__ x,
                                                       const float* __restrict__ W,
                                                       const float* __restrict__ a_src,
                                                       const float* __restrict__ a_dst) {
    extern __shared__ char smem[];
    __nv_bfloat16* sAh = (__nv_bfloat16*)smem;
    __nv_bfloat16* sAl = sAh + 128 * LDT;
    __nv_bfloat16* sWh = sAl + 128 * LDT;
    __nv_bfloat16* sWl = sWh + 128 * LDT;

    const int tid = threadIdx.x;
    const int wid = tid >> 5;
    const int lane = tid & 31;
    const int rowBase = blockIdx.x * 128;

    for (int it = tid; it < 4096; it += 256) {
        int row = it >> 5;
        int col = (it & 31) * 4;
        int grow = rowBase + row;
        float4 v = (grow < GN) ? *(const float4*)(x + (size_t)grow * IND + col)
                               : make_float4(0.f, 0.f, 0.f, 0.f);
        __nv_bfloat16 h0, h1, h2, h3, l0, l1, l2, l3;
        split2(v.x, h0, l0); split2(v.y, h1, l1);
        split2(v.z, h2, l2); split2(v.w, h3, l3);
        int o = row * LDT + col;
        *(__nv_bfloat162*)(sAh + o)     = __nv_bfloat162(h0, h1);
        *(__nv_bfloat162*)(sAh + o + 2) = __nv_bfloat162(h2, h3);
        *(__nv_bfloat162*)(sAl + o)     = __nv_bfloat162(l0, l1);
        *(__nv_bfloat162*)(sAl + o + 2) = __nv_bfloat162(l2, l3);

        float4 w = *(const float4*)(W + (size_t)row * IND + col);
        split2(w.x, h0, l0); split2(w.y, h1, l1);
        split2(w.z, h2, l2); split2(w.w, h3, l3);
        *(__nv_bfloat162*)(sWh + o)     = __nv_bfloat162(h0, h1);
        *(__nv_bfloat162*)(sWh + o + 2) = __nv_bfloat162(h2, h3);
        *(__nv_bfloat162*)(sWl + o)     = __nv_bfloat162(l0, l1);
        *(__nv_bfloat162*)(sWl + o + 2) = __nv_bfloat162(l2, l3);
    }
    __syncthreads();

    float acc[64];
#pragma unroll
    for (int i = 0; i < 64; i++) acc[i] = 0.f;

    const int aRow = wid * 16 + (lane & 15);
    const int aKH  = (lane >> 4) * 8;
    const int bRow = (lane & 7) + ((lane >> 4) << 3);
    const int bKH  = ((lane >> 3) & 1) * 8;

#pragma unroll
    for (int p = 0; p < 3; p++) {
        const __nv_bfloat16* At = (p == 2) ? sAl : sAh;
        const __nv_bfloat16* Bt = (p == 1) ? sWl : sWh;
        uint32_t aBase = smem_u32(At) + (uint32_t)(aRow * LDT + aKH) * 2u;
        uint32_t bBase = smem_u32(Bt) + (uint32_t)(bRow * LDT + bKH) * 2u;
#pragma unroll
        for (int ks = 0; ks < 8; ks++) {
            uint32_t a0, a1, a2, a3;
            ldsm4(a0, a1, a2, a3, aBase + ks * 32);
#pragma unroll
            for (int tp = 0; tp < 8; tp++) {
                uint32_t b0, b1, b2, b3;
                ldsm4(b0, b1, b2, b3, bBase + (uint32_t)(tp * 16 * LDT) * 2u + ks * 32);
                mma16816(acc + (2 * tp) * 4,     a0, a1, a2, a3, b0, b1);
                mma16816(acc + (2 * tp + 1) * 4, a0, a1, a2, a3, b2, b3);
            }
        }
    }

    const int g = lane >> 2, tg = lane & 3;
    const int rA = rowBase + wid * 16 + g;
    const int rB = rA + 8;
    const bool vA = rA < GN, vB = rB < GN;

    if (vA) {
        float* hp = g_h + (size_t)rA * HO;
#pragma unroll
        for (int t = 0; t < 16; t++)
            *(float2*)(hp + t * 8 + tg * 2) = make_float2(acc[t * 4], acc[t * 4 + 1]);
    }
    if (vB) {
        float* hp = g_h + (size_t)rB * HO;
#pragma unroll
        for (int t = 0; t < 16; t++)
            *(float2*)(hp + t * 8 + tg * 2) = make_float2(acc[t * 4 + 2], acc[t * 4 + 3]);
    }

    float kAs = 0.f, kAd = 0.f, kBs = 0.f, kBd = 0.f;
#pragma unroll
    for (int h = 0; h < 4; h++) {
        float pAs = 0.f, pAd = 0.f, pBs = 0.f, pBd = 0.f;
#pragma unroll
        for (int tt = 0; tt < 4; tt++) {
            int t = h * 4 + tt;
            int col = t * 8 + tg * 2;
            float as0 = a_src[col], as1 = a_src[col + 1];
            float ad0 = a_dst[col], ad1 = a_dst[col + 1];
            pAs += acc[t * 4] * as0 + acc[t * 4 + 1] * as1;
            pAd += acc[t * 4] * ad0 + acc[t * 4 + 1] * ad1;
            pBs += acc[t * 4 + 2] * as0 + acc[t * 4 + 3] * as1;
            pBd += acc[t * 4 + 2] * ad0 + acc[t * 4 + 3] * ad1;
        }
        pAs += __shfl_xor_sync(0xFFFFFFFFu, pAs, 1);
        pAs += __shfl_xor_sync(0xFFFFFFFFu, pAs, 2);
        pAd += __shfl_xor_sync(0xFFFFFFFFu, pAd, 1);
        pAd += __shfl_xor_sync(0xFFFFFFFFu, pAd, 2);
        pBs += __shfl_xor_sync(0xFFFFFFFFu, pBs, 1);
        pBs += __shfl_xor_sync(0xFFFFFFFFu, pBs, 2);
        pBd += __shfl_xor_sync(0xFFFFFFFFu, pBd, 1);
        pBd += __shfl_xor_sync(0xFFFFFFFFu, pBd, 2);
        if (tg == h) { kAs = pAs; kAd = pAd; kBs = pBs; kBd = pBd; }
    }
    if (vA) {
        ((float*)&g_ssrc[rA])[tg] = kAs;
        ((float*)&g_sddn[2 * rA])[tg] = kAd;
    }
    if (vB) {
        ((float*)&g_ssrc[rB])[tg] = kBs;
        ((float*)&g_sddn[2 * rB])[tg] = kBd;
    }
}

// ---------------- scan block sums (tiny, serial) ----------------
__global__ void scan2_kernel() {
    if (threadIdx.x == 0 && blockIdx.x == 0) {
        int run = 0;
        for (int b = 0; b < NB; b++) { run += g_bsum[b]; g_bpref[b] = run; }
    }
}

// ---------------- finalize exclusive row offsets + cursors ----------------
__global__ void scan3_kernel() {
    int i = blockIdx.x * blockDim.x + threadIdx.x;
    if (i >= GN) return;
    int b = i >> 10;
    int excl = g_incl[i] - g_deg[i] + (b > 0 ? g_bpref[b - 1] : 0);
    g_rowoff[i] = excl;
    g_cursor[i] = excl;
    if (i == 0) g_rowoff[GN] = GE;
}

// ---------------- scatter edges into CSR (2 edges/thread, int2 payload) ---
__global__ void scatter_kernel(const int* __restrict__ ei,
                               const float* __restrict__ rw) {
    int i = blockIdx.x * blockDim.x + threadIdx.x;
    if (i >= GE / 2) return;
    int2 s2 = ((const int2*)ei)[i];
    int2 d2 = ((const int2*)(ei + GE))[i];
    float2 w2 = ((const float2*)rw)[i];
    int p0 = atomicAdd(&g_cursor[d2.x], 1);
    g_csr[p0] = make_int2(s2.x, __float_as_int(__logf(w2.x + 1e-8f)));
    int p1 = atomicAdd(&g_cursor[d2.y], 1);
    g_csr[p1] = make_int2(s2.y, __float_as_int(__logf(w2.y + 1e-8f)));
}

// ---------------- atomic-free aggregation, one warp per dst node ----------
__global__ void __launch_bounds__(256) agg_kernel(float* __restrict__ out) {
    int node = (blockIdx.x * blockDim.x + threadIdx.x) >> 5;
    int lane = threadIdx.x & 31;
    if (node >= GN) return;
    int head = lane >> 3;

    int beg = g_rowoff[node];
    int end = g_rowoff[node + 1];
    float sd = ((const float*)&g_sddn[2 * node])[head];

    const float4* h4 = (const float4*)g_h;
    const float* ssrc_f = (const float*)g_ssrc;

    float denom = 0.f;
    float4 acc = make_float4(0.f, 0.f, 0.f, 0.f);

    int e = beg;
    // 2-edge pipelined main loop: both gathers in flight together
    for (; e + 2 <= end; e += 2) {
        int2 c0 = g_csr[e];
        int2 c1 = g_csr[e + 1];
        float4 h0 = h4[(size_t)c0.x * (HO / 4) + lane];
        float4 h1 = h4[(size_t)c1.x * (HO / 4) + lane];
        float a0 = ssrc_f[(size_t)c0.x * 4 + head];
        float a1 = ssrc_f[(size_t)c1.x * 4 + head];
        float ex0 = lexp(a0 + sd + __int_as_float(c0.y));
        float ex1 = lexp(a1 + sd + __int_as_float(c1.y));
        denom += ex0 + ex1;
        acc.x = fmaf(ex0, h0.x, fmaf(ex1, h1.x, acc.x));
        acc.y = fmaf(ex0, h0.y, fmaf(ex1, h1.y, acc.y));
        acc.z = fmaf(ex0, h0.z, fmaf(ex1, h1.z, acc.z));
        acc.w = fmaf(ex0, h0.w, fmaf(ex1, h1.w, acc.w));
    }
    if (e < end) {
        int2 c0 = g_csr[e];
        float4 h0 = h4[(size_t)c0.x * (HO / 4) + lane];
        float a0 = ssrc_f[(size_t)c0.x * 4 + head];
        float ex0 = lexp(a0 + sd + __int_as_float(c0.y));
        denom += ex0;
        acc.x = fmaf(ex0, h0.x, acc.x);
        acc.y = fmaf(ex0, h0.y, acc.y);
        acc.z = fmaf(ex0, h0.z, acc.z);
        acc.w = fmaf(ex0, h0.w, acc.w);
    }

    float inv = 1.f / (denom + 1e-8f);
    float4 o = make_float4(acc.x * inv, acc.y * inv, acc.z * inv, acc.w * inv);
    ((float4*)out)[(size_t)node * (HO / 4) + lane] = o;
    if ((lane & 7) == 0) ((float*)&g_sddn[2 * node + 1])[head] = denom;
}

// ---------------- alpha output (original edge order) ----------------
__global__ void alpha_kernel(const int* __restrict__ ei,
                             const float* __restrict__ rw,
                             float4* __restrict__ alpha_out) {
    int e = blockIdx.x * blockDim.x + threadIdx.x;
    if (e >= GE) return;
    int s = ei[e];
    int d = ei[GE + e];
    float lw = __logf(rw[e] + 1e-8f);
    float4 a = g_ssrc[s];
    float4 b = g_sddn[2 * d];      // sdst
    float4 dn = g_sddn[2 * d + 1]; // denom (adjacent 16B -> same 32B sector)
    float4 al;
    al.x = lexp(a.x + b.x + lw) / (dn.x + 1e-8f);
    al.y = lexp(a.y + b.y + lw) / (dn.y + 1e-8f);
    al.z = lexp(a.z + b.z + lw) / (dn.z + 1e-8f);
    al.w = lexp(a.w + b.w + lw) / (dn.w + 1e-8f);
    alpha_out[e] = al;
}

// ---------------- launch ----------------
#define GEMM_SMEM (4 * 128 * LDT * 2)

extern "C" void kernel_launch(void* const* d_in, const int* in_sizes, int n_in,
                              void* d_out, int out_size) {
    const float* x     = (const float*)d_in[0];
    const float* W     = (const float*)d_in[1];
    const float* a_src = (const float*)d_in[2];
    const float* a_dst = (const float*)d_in[3];
    const int*   ei    = (const int*)d_in[4];
    const float* rw    = (const float*)d_in[5];
    float* out = (float*)d_out;

    int writeAlpha = (out_size >= GN * HO + GE * HEADS) ? 1 : 0;
    float4* alpha_out = (float4*)(out + (size_t)GN * HO);

    cudaFuncSetAttribute(gemm_mma_kernel,
                         cudaFuncAttributeMaxDynamicSharedMemorySize, GEMM_SMEM);

    // order chosen so the GEMM is the 4th launch (ncu's fixed profile slot)
    zero_deg_kernel<<<(GN + 255) / 256, 256>>>();
    hist_kernel<<<(GE / 2 + 255) / 256, 256>>>(ei);
    scan1_kernel<<<NB, 1024>>>();
    gemm_mma_kernel<<<(GN + 127) / 128, 256, GEMM_SMEM>>>(x, W, a_src, a_dst);
    scan2_kernel<<<1, 32>>>();
    scan3_kernel<<<(GN + 255) / 256, 256>>>();
    scatter_kernel<<<(GE / 2 + 255) / 256, 256>>>(ei, rw);
    agg_kernel<<<(int)(((long long)GN * 32 + 255) / 256), 256>>>(out);
    if (writeAlpha)
        alpha_kernel<<<(GE + 255) / 256, 256>>>(ei, rw, alpha_out);
}

// round 9
// speedup vs baseline: 1.9975x; 1.1809x over previous
#include <cuda_runtime.h>
#include <cuda_bf16.h>
#include <cstdint>

#define GN 100000
#define GE 1600000
#define HEADS 4
#define ODIM 32
#define HO 128   /* HEADS*ODIM */
#define IND 128
#define NB 98    /* ceil(GN/1024) scan blocks */
#define LDT 136  /* padded bf16 row stride for smem tiles */

// ---------------- scratch (device globals; no allocation allowed) ----------
__device__ float  g_h[(size_t)GN * HO];          // projected features, 51.2 MB
__device__ float4 g_ssrc[GN];                    // per-node src scores (4 heads)
__device__ float4 g_sddn[2 * GN];                // [2n]=sdst, [2n+1]=denom (32B pair)
__device__ int    g_deg[GN];                     // in-degree histogram
__device__ int    g_incl[GN];                    // per-block inclusive scan
__device__ int    g_bsum[NB];                    // block sums
__device__ int    g_bpref[NB];                   // inclusive scan of block sums
__device__ int    g_rowoff[GN + 1];              // CSR row offsets (by dst)
__device__ int    g_cursor[GN];                  // scatter cursors
__device__ int2   g_csr[GE];                     // CSR: (src, log-weight bits)

// ---------------- helpers ----------------
__device__ __forceinline__ uint32_t smem_u32(const void* p) {
    uint32_t a;
    asm("{ .reg .u64 t; cvta.to.shared.u64 t, %1; cvt.u32.u64 %0, t; }"
        : "=r"(a) : "l"(p));
    return a;
}
__device__ __forceinline__ void ldsm4(uint32_t& r0, uint32_t& r1,
                                      uint32_t& r2, uint32_t& r3, uint32_t addr) {
    asm volatile("ldmatrix.sync.aligned.m8n8.x4.shared.b16 {%0,%1,%2,%3}, [%4];"
                 : "=r"(r0), "=r"(r1), "=r"(r2), "=r"(r3) : "r"(addr));
}
__device__ __forceinline__ void mma16816(float* c, uint32_t a0, uint32_t a1,
                                         uint32_t a2, uint32_t a3,
                                         uint32_t b0, uint32_t b1) {
    asm volatile("mma.sync.aligned.m16n8k16.row.col.f32.bf16.bf16.f32 "
                 "{%0,%1,%2,%3}, {%4,%5,%6,%7}, {%8,%9}, {%0,%1,%2,%3};"
                 : "+f"(c[0]), "+f"(c[1]), "+f"(c[2]), "+f"(c[3])
                 : "r"(a0), "r"(a1), "r"(a2), "r"(a3), "r"(b0), "r"(b1));
}
__device__ __forceinline__ void split2(float v, __nv_bfloat16& h, __nv_bfloat16& l) {
    h = __float2bfloat16(v);
    l = __float2bfloat16(v - __bfloat162float(h));
}
__device__ __forceinline__ float lexp(float v) {
    v = (v >= 0.f) ? v : 0.2f * v;   // leaky_relu(0.2)
    return __expf(v);                // scores bounded; no max-shift needed
}

// ---------------- zero degree counters ----------------
__global__ void zero_deg_kernel() {
    int i = blockIdx.x * blockDim.x + threadIdx.x;
    if (i < GN) g_deg[i] = 0;
}

// ---------------- degree histogram over dst (2 edges/thread) --------------
__global__ void hist_kernel(const int* __restrict__ ei) {
    int i = blockIdx.x * blockDim.x + threadIdx.x;
    if (i >= GE / 2) return;
    int2 d2 = ((const int2*)(ei + GE))[i];
    atomicAdd(&g_deg[d2.x], 1);
    atomicAdd(&g_deg[d2.y], 1);
}

// ---------------- per-block inclusive scan ----------------
__global__ void __launch_bounds__(1024) scan1_kernel() {
    int i = blockIdx.x * 1024 + threadIdx.x;
    int v = (i < GN) ? g_deg[i] : 0;
    int lane = threadIdx.x & 31, w = threadIdx.x >> 5;
    int s = v;
#pragma unroll
    for (int o = 1; o < 32; o <<= 1) {
        int t = __shfl_up_sync(0xFFFFFFFFu, s, o);
        if (lane >= o) s += t;
    }
    __shared__ int ws[32];
    if (lane == 31) ws[w] = s;
    __syncthreads();
    if (w == 0) {
        int t = ws[lane];
#pragma unroll
        for (int o = 1; o < 32; o <<= 1) {
            int u = __shfl_up_sync(0xFFFFFFFFu, t, o);
            if (lane >= o) t += u;
        }
        ws[lane] = t;
    }
    __syncthreads();
    if (w > 0) s += ws[w - 1];
    if (i < GN) g_incl[i] = s;
    if (threadIdx.x == 1023) g_bsum[blockIdx.x] = s;
}

// ---- h = x @ W^T via mma.sync split-bf16, 512 thr / 16 warps -------------
// warp tile: 16 rows x 64 cols (rg = wid>>1 row group, ch = wid&1 col half)
__global__ void __launch_bounds__(512) gemm_mma_kernel(const float* __restrict__ x,
                                                       const float* __restrict__ W,
                                                       const float* __restrict__ a_src,
                                                       const float* __restrict__ a_dst) {
    extern __shared__ char smem[];
    __nv_bfloat16* sAh = (__nv_bfloat16*)smem;
    __nv_bfloat16* sAl = sAh + 128 * LDT;
    __nv_bfloat16* sWh = sAl + 128 * LDT;
    __nv_bfloat16* sWl = sWh + 128 * LDT;

    const int tid = threadIdx.x;
    const int wid = tid >> 5;
    const int lane = tid & 31;
    const int rg = wid >> 1;        // row group 0..7
    const int ch = wid & 1;         // col half 0..1
    const int rowBase = blockIdx.x * 128;

    for (int it = tid; it < 4096; it += 512) {
        int row = it >> 5;
        int col = (it & 31) * 4;
        int grow = rowBase + row;
        float4 v = (grow < GN) ? *(const float4*)(x + (size_t)grow * IND + col)
                               : make_float4(0.f, 0.f, 0.f, 0.f);
        __nv_bfloat16 h0, h1, h2, h3, l0, l1, l2, l3;
        split2(v.x, h0, l0); split2(v.y, h1, l1);
        split2(v.z, h2, l2); split2(v.w, h3, l3);
        int o = row * LDT + col;
        *(__nv_bfloat162*)(sAh + o)     = __nv_bfloat162(h0, h1);
        *(__nv_bfloat162*)(sAh + o + 2) = __nv_bfloat162(h2, h3);
        *(__nv_bfloat162*)(sAl + o)     = __nv_bfloat162(l0, l1);
        *(__nv_bfloat162*)(sAl + o + 2) = __nv_bfloat162(l2, l3);

        float4 w = *(const float4*)(W + (size_t)row * IND + col);
        split2(w.x, h0, l0); split2(w.y, h1, l1);
        split2(w.z, h2, l2); split2(w.w, h3, l3);
        *(__nv_bfloat162*)(sWh + o)     = __nv_bfloat162(h0, h1);
        *(__nv_bfloat162*)(sWh + o + 2) = __nv_bfloat162(h2, h3);
        *(__nv_bfloat162*)(sWl + o)     = __nv_bfloat162(l0, l1);
        *(__nv_bfloat162*)(sWl + o + 2) = __nv_bfloat162(l2, l3);
    }
    __syncthreads();

    float acc[32];
#pragma unroll
    for (int i = 0; i < 32; i++) acc[i] = 0.f;

    const int aRow = rg * 16 + (lane & 15);
    const int aKH  = (lane >> 4) * 8;
    const int bRow = ch * 64 + (lane & 7) + ((lane >> 4) << 3);
    const int bKH  = ((lane >> 3) & 1) * 8;

#pragma unroll
    for (int p = 0; p < 3; p++) {
        const __nv_bfloat16* At = (p == 2) ? sAl : sAh;
        const __nv_bfloat16* Bt = (p == 1) ? sWl : sWh;
        uint32_t aBase = smem_u32(At) + (uint32_t)(aRow * LDT + aKH) * 2u;
        uint32_t bBase = smem_u32(Bt) + (uint32_t)(bRow * LDT + bKH) * 2u;
#pragma unroll
        for (int ks = 0; ks < 8; ks++) {
            uint32_t a0, a1, a2, a3;
            ldsm4(a0, a1, a2, a3, aBase + ks * 32);
#pragma unroll
            for (int tp = 0; tp < 4; tp++) {
                uint32_t b0, b1, b2, b3;
                ldsm4(b0, b1, b2, b3, bBase + (uint32_t)(tp * 16 * LDT) * 2u + ks * 32);
                mma16816(acc + (2 * tp) * 4,     a0, a1, a2, a3, b0, b1);
                mma16816(acc + (2 * tp + 1) * 4, a0, a1, a2, a3, b2, b3);
            }
        }
    }

    // epilogue: col tile t (0..7) covers cols ch*64 + t*8 + tg*2
    const int g = lane >> 2, tg = lane & 3;
    const int rA = rowBase + rg * 16 + g;
    const int rB = rA + 8;
    const bool vA = rA < GN, vB = rB < GN;
    const int colOff = ch * 64;

    if (vA) {
        float* hp = g_h + (size_t)rA * HO + colOff;
#pragma unroll
        for (int t = 0; t < 8; t++)
            *(float2*)(hp + t * 8 + tg * 2) = make_float2(acc[t * 4], acc[t * 4 + 1]);
    }
    if (vB) {
        float* hp = g_h + (size_t)rB * HO + colOff;
#pragma unroll
        for (int t = 0; t < 8; t++)
            *(float2*)(hp + t * 8 + tg * 2) = make_float2(acc[t * 4 + 2], acc[t * 4 + 3]);
    }

    // fused per-node scores: this warp's 64 cols = heads {ch*2, ch*2+1}
#pragma unroll
    for (int hh = 0; hh < 2; hh++) {
        float pAs = 0.f, pAd = 0.f, pBs = 0.f, pBd = 0.f;
#pragma unroll
        for (int tt = 0; tt < 4; tt++) {
            int t = hh * 4 + tt;
            int col = colOff + t * 8 + tg * 2;
            float as0 = a_src[col], as1 = a_src[col + 1];
            float ad0 = a_dst[col], ad1 = a_dst[col + 1];
            pAs += acc[t * 4] * as0 + acc[t * 4 + 1] * as1;
            pAd += acc[t * 4] * ad0 + acc[t * 4 + 1] * ad1;
            pBs += acc[t * 4 + 2] * as0 + acc[t * 4 + 3] * as1;
            pBd += acc[t * 4 + 2] * ad0 + acc[t * 4 + 3] * ad1;
        }
        pAs += __shfl_xor_sync(0xFFFFFFFFu, pAs, 1);
        pAs += __shfl_xor_sync(0xFFFFFFFFu, pAs, 2);
        pAd += __shfl_xor_sync(0xFFFFFFFFu, pAd, 1);
        pAd += __shfl_xor_sync(0xFFFFFFFFu, pAd, 2);
        pBs += __shfl_xor_sync(0xFFFFFFFFu, pBs, 1);
        pBs += __shfl_xor_sync(0xFFFFFFFFu, pBs, 2);
        pBd += __shfl_xor_sync(0xFFFFFFFFu, pBd, 1);
        pBd += __shfl_xor_sync(0xFFFFFFFFu, pBd, 2);
        if (tg == hh) {
            int hcol = ch * 2 + hh;
            if (vA) {
                ((float*)&g_ssrc[rA])[hcol] = pAs;
                ((float*)&g_sddn[2 * rA])[hcol] = pAd;
            }
            if (vB) {
                ((float*)&g_ssrc[rB])[hcol] = pBs;
                ((float*)&g_sddn[2 * rB])[hcol] = pBd;
            }
        }
    }
}

// ---------------- scan block sums (tiny, serial) ----------------
__global__ void scan2_kernel() {
    if (threadIdx.x == 0 && blockIdx.x == 0) {
        int run = 0;
        for (int b = 0; b < NB; b++) { run += g_bsum[b]; g_bpref[b] = run; }
    }
}

// ---------------- finalize exclusive row offsets + cursors ----------------
__global__ void scan3_kernel() {
    int i = blockIdx.x * blockDim.x + threadIdx.x;
    if (i >= GN) return;
    int b = i >> 10;
    int excl = g_incl[i] - g_deg[i] + (b > 0 ? g_bpref[b - 1] : 0);
    g_rowoff[i] = excl;
    g_cursor[i] = excl;
    if (i == 0) g_rowoff[GN] = GE;
}

// ---------------- scatter edges into CSR (2 edges/thread, int2 payload) ---
__global__ void scatter_kernel(const int* __restrict__ ei,
                               const float* __restrict__ rw) {
    int i = blockIdx.x * blockDim.x + threadIdx.x;
    if (i >= GE / 2) return;
    int2 s2 = ((const int2*)ei)[i];
    int2 d2 = ((const int2*)(ei + GE))[i];
    float2 w2 = ((const float2*)rw)[i];
    int p0 = atomicAdd(&g_cursor[d2.x], 1);
    g_csr[p0] = make_int2(s2.x, __float_as_int(__logf(w2.x + 1e-8f)));
    int p1 = atomicAdd(&g_cursor[d2.y], 1);
    g_csr[p1] = make_int2(s2.y, __float_as_int(__logf(w2.y + 1e-8f)));
}

// ---------------- atomic-free aggregation, one warp per dst node ----------
__global__ void __launch_bounds__(256) agg_kernel(float* __restrict__ out) {
    int node = (blockIdx.x * blockDim.x + threadIdx.x) >> 5;
    int lane = threadIdx.x & 31;
    if (node >= GN) return;
    int head = lane >> 3;

    int beg = g_rowoff[node];
    int end = g_rowoff[node + 1];
    float sd = ((const float*)&g_sddn[2 * node])[head];

    const float4* h4 = (const float4*)g_h;
    const float* ssrc_f = (const float*)g_ssrc;

    float denom = 0.f;
    float4 acc = make_float4(0.f, 0.f, 0.f, 0.f);

    int e = beg;
    for (; e + 2 <= end; e += 2) {
        int2 c0 = g_csr[e];
        int2 c1 = g_csr[e + 1];
        float4 h0 = h4[(size_t)c0.x * (HO / 4) + lane];
        float4 h1 = h4[(size_t)c1.x * (HO / 4) + lane];
        float a0 = ssrc_f[(size_t)c0.x * 4 + head];
        float a1 = ssrc_f[(size_t)c1.x * 4 + head];
        float ex0 = lexp(a0 + sd + __int_as_float(c0.y));
        float ex1 = lexp(a1 + sd + __int_as_float(c1.y));
        denom += ex0 + ex1;
        acc.x = fmaf(ex0, h0.x, fmaf(ex1, h1.x, acc.x));
        acc.y = fmaf(ex0, h0.y, fmaf(ex1, h1.y, acc.y));
        acc.z = fmaf(ex0, h0.z, fmaf(ex1, h1.z, acc.z));
        acc.w = fmaf(ex0, h0.w, fmaf(ex1, h1.w, acc.w));
    }
    if (e < end) {
        int2 c0 = g_csr[e];
        float4 h0 = h4[(size_t)c0.x * (HO / 4) + lane];
        float a0 = ssrc_f[(size_t)c0.x * 4 + head];
        float ex0 = lexp(a0 + sd + __int_as_float(c0.y));
        denom += ex0;
        acc.x = fmaf(ex0, h0.x, acc.x);
        acc.y = fmaf(ex0, h0.y, acc.y);
        acc.z = fmaf(ex0, h0.z, acc.z);
        acc.w = fmaf(ex0, h0.w, acc.w);
    }

    float inv = 1.f / (denom + 1e-8f);
    float4 o = make_float4(acc.x * inv, acc.y * inv, acc.z * inv, acc.w * inv);
    ((float4*)out)[(size_t)node * (HO / 4) + lane] = o;
    if ((lane & 7) == 0) ((float*)&g_sddn[2 * node + 1])[head] = denom;
}

// ---------------- alpha output (original edge order) ----------------
__global__ void alpha_kernel(const int* __restrict__ ei,
                             const float* __restrict__ rw,
                             float4* __restrict__ alpha_out) {
    int e = blockIdx.x * blockDim.x + threadIdx.x;
    if (e >= GE) return;
    int s = ei[e];
    int d = ei[GE + e];
    float lw = __logf(rw[e] + 1e-8f);
    float4 a = g_ssrc[s];
    float4 b = g_sddn[2 * d];      // sdst
    float4 dn = g_sddn[2 * d + 1]; // denom (adjacent 16B -> same 32B sector)
    float4 al;
    al.x = lexp(a.x + b.x + lw) / (dn.x + 1e-8f);
    al.y = lexp(a.y + b.y + lw) / (dn.y + 1e-8f);
    al.z = lexp(a.z + b.z + lw) / (dn.z + 1e-8f);
    al.w = lexp(a.w + b.w + lw) / (dn.w + 1e-8f);
    alpha_out[e] = al;
}

// ---------------- launch ----------------
#define GEMM_SMEM (4 * 128 * LDT * 2)

extern "C" void kernel_launch(void* const* d_in, const int* in_sizes, int n_in,
                              void* d_out, int out_size) {
    const float* x     = (const float*)d_in[0];
    const float* W     = (const float*)d_in[1];
    const float* a_src = (const float*)d_in[2];
    const float* a_dst = (const float*)d_in[3];
    const int*   ei    = (const int*)d_in[4];
    const float* rw    = (const float*)d_in[5];
    float* out = (float*)d_out;

    int writeAlpha = (out_size >= GN * HO + GE * HEADS) ? 1 : 0;
    float4* alpha_out = (float4*)(out + (size_t)GN * HO);

    cudaFuncSetAttribute(gemm_mma_kernel,
                         cudaFuncAttributeMaxDynamicSharedMemorySize, GEMM_SMEM);

    // order chosen so the GEMM is the 4th launch (ncu's fixed profile slot)
    zero_deg_kernel<<<(GN + 255) / 256, 256>>>();
    hist_kernel<<<(GE / 2 + 255) / 256, 256>>>(ei);
    scan1_kernel<<<NB, 1024>>>();
    gemm_mma_kernel<<<(GN + 127) / 128, 512, GEMM_SMEM>>>(x, W, a_src, a_dst);
    scan2_kernel<<<1, 32>>>();
    scan3_kernel<<<(GN + 255) / 256, 256>>>();
    scatter_kernel<<<(GE / 2 + 255) / 256, 256>>>(ei, rw);
    agg_kernel<<<(int)(((long long)GN * 32 + 255) / 256), 256>>>(out);
    if (writeAlpha)
        alpha_kernel<<<(GE + 255) / 256, 256>>>(ei, rw, alpha_out);
}